// round 10
// baseline (speedup 1.0000x reference)
#include <cuda_runtime.h>

#define N_NODES 50000
#define N_EDGES 800000
#define DIM 96

typedef unsigned long long ull;

// Scratch (__device__ globals per allocation-free rule)
__device__ __align__(128) float g_agg[N_NODES * DIM];   // 19.2 MB
__device__ float g_deg[N_NODES];

// ---------------------------------------------------------------------------
// Scatter: one thread per (edge, float4 chunk); 24 chunks/edge.
// red.global.add.v4.f32 into g_agg (L2-resident). LTS-cap bound.
// ---------------------------------------------------------------------------
__global__ void scatter_kernel(const float* __restrict__ x,
                               const int* __restrict__ edge_index) {
    long long t = (long long)blockIdx.x * blockDim.x + threadIdx.x;
    int e = (int)(t / 24);
    int c = (int)(t % 24);
    if (e >= N_EDGES) return;

    int src = __ldg(&edge_index[e]);
    int dst = __ldg(&edge_index[N_EDGES + e]);

    float4 v = ((const float4*)(x + (size_t)src * DIM))[c];
    float* p = g_agg + (size_t)dst * DIM + c * 4;
    asm volatile("red.global.add.v4.f32 [%0], {%1,%2,%3,%4};"
                 :: "l"(p), "f"(v.x), "f"(v.y), "f"(v.z), "f"(v.w) : "memory");
    if (c == 0) atomicAdd(&g_deg[dst], 1.0f);
}

// ---------------------------------------------------------------------------
// Combined GEMM: out = [x | g_agg/max(deg,1)] @ [Ws | Wn]^T + (bs+bn)
// BM=64, BN=96; K=192 as two 96-wide smem stages; 128 threads; TM=8 x TN=6.
// Smem is K-MAJOR in packed pairs: sA2[kp][m], sB2[kp][j] (8B cells), so the
// inner loop is 4 broadcast LDS.128 (A) + 3 contiguous LDS.128 (B) per kp.
// Accumulators are packed fma.rn.f32x2 pairs carried across both stages.
// ---------------------------------------------------------------------------
#define BM 64
#define BN 96
#define TM 8
#define TN 6
#define GT 128
#define GEMM_BLOCKS ((N_NODES + BM - 1) / BM)   // 782
#define KP 48   // k-pairs per stage (96/2)

__device__ __forceinline__ void ffma2(ull& d, ull a, ull b) {
    asm("fma.rn.f32x2 %0, %1, %2, %0;" : "+l"(d) : "l"(a), "l"(b));
}
__device__ __forceinline__ ull packf2(float lo, float hi) {
    ull r;
    asm("mov.b64 %0, {%1, %2};" : "=l"(r) : "f"(lo), "f"(hi));
    return r;
}

__global__ void gemm_kernel(const float* __restrict__ x,
                            const float* __restrict__ Ws,
                            const float* __restrict__ bs,
                            const float* __restrict__ Wn,
                            const float* __restrict__ bn,
                            float* __restrict__ out) {
    __shared__ __align__(16) ull sA2[KP][BM];   // 24.0 KB
    __shared__ __align__(16) ull sB2[KP][BN];   // 36.0 KB
    __shared__ float sInv[BM];

    const int tid = threadIdx.x;
    const int tx = tid % (BN / TN);     // 0..15 column group
    const int ty = tid / (BN / TN);     // 0..7  row group
    const int rowBase = blockIdx.x * BM;

    if (tid < BM) {
        int row = rowBase + tid;
        float d = (row < N_NODES) ? g_deg[row] : 1.0f;
        sInv[tid] = 1.0f / fmaxf(d, 1.0f);
    }

    ull acc2[TM][TN];
    #pragma unroll
    for (int i = 0; i < TM; i++)
        #pragma unroll
        for (int j = 0; j < TN; j++) acc2[i][j] = 0ULL;

    #pragma unroll 1
    for (int stage = 0; stage < 2; stage++) {
        const float* __restrict__ A = stage ? g_agg : x;
        const float* __restrict__ W = stage ? Wn : Ws;
        if (stage) __syncthreads();    // protect smem reuse across stages

        // stage A (k-major): 24 q-chunks x 64 m; lanes take consecutive m.
        #pragma unroll
        for (int it = 0; it < 12; it++) {
            int idx = it * GT + tid;
            int q = idx >> 6;          // float4 index 0..23
            int m = idx & 63;
            int row = rowBase + m;
            float4 v = make_float4(0.f, 0.f, 0.f, 0.f);
            if (row < N_NODES) {
                v = ((const float4*)(A + (size_t)row * DIM))[q];
                if (stage) {
                    float inv = sInv[m];
                    v.x *= inv; v.y *= inv; v.z *= inv; v.w *= inv;
                }
            }
            sA2[2 * q + 0][m] = packf2(v.x, v.y);
            sA2[2 * q + 1][m] = packf2(v.z, v.w);
        }
        // stage B (k-major): 24 q-chunks x 96 j; lanes take consecutive j.
        #pragma unroll
        for (int it = 0; it < 18; it++) {
            int idx = it * GT + tid;
            int q = idx / BN;          // 0..23
            int j = idx % BN;
            float4 v = *(const float4*)(W + (size_t)j * DIM + q * 4);
            sB2[2 * q + 0][j] = packf2(v.x, v.y);
            sB2[2 * q + 1][j] = packf2(v.z, v.w);
        }
        __syncthreads();

        #pragma unroll 4
        for (int kp = 0; kp < KP; kp++) {
            const ulonglong2* pa = (const ulonglong2*)&sA2[kp][ty * TM];
            const ulonglong2* pb = (const ulonglong2*)&sB2[kp][tx * TN];
            ulonglong2 A0 = pa[0], A1 = pa[1], A2v = pa[2], A3 = pa[3];
            ulonglong2 B0 = pb[0], B1 = pb[1], B2v = pb[2];
            ull a2[TM] = {A0.x, A0.y, A1.x, A1.y, A2v.x, A2v.y, A3.x, A3.y};
            ull b2[TN] = {B0.x, B0.y, B1.x, B1.y, B2v.x, B2v.y};
            #pragma unroll
            for (int i = 0; i < TM; i++)
                #pragma unroll
                for (int j = 0; j < TN; j++)
                    ffma2(acc2[i][j], a2[i], b2[j]);
        }
    }

    // epilogue: reduce pair sums, fused bias, float2 stores
    const int colBase = tx * TN;
    float biasv[TN];
    #pragma unroll
    for (int j = 0; j < TN; j++)
        biasv[j] = bs[colBase + j] + bn[colBase + j];

    #pragma unroll
    for (int i = 0; i < TM; i++) {
        int row = rowBase + ty * TM + i;
        if (row < N_NODES) {
            float* op = out + (size_t)row * DIM + colBase;
            #pragma unroll
            for (int j2 = 0; j2 < TN / 2; j2++) {
                ull u0 = acc2[i][2 * j2 + 0];
                ull u1 = acc2[i][2 * j2 + 1];
                float2 v;
                v.x = __uint_as_float((unsigned)(u0 & 0xffffffffu)) +
                      __uint_as_float((unsigned)(u0 >> 32)) + biasv[2 * j2 + 0];
                v.y = __uint_as_float((unsigned)(u1 & 0xffffffffu)) +
                      __uint_as_float((unsigned)(u1 >> 32)) + biasv[2 * j2 + 1];
                *(float2*)(op + 2 * j2) = v;
            }
        }
    }
}

// ---------------------------------------------------------------------------
extern "C" void kernel_launch(void* const* d_in, const int* in_sizes, int n_in,
                              void* d_out, int out_size) {
    const float* x        = (const float*)d_in[0];
    const int*   ei       = (const int*)d_in[1];
    const float* W_self   = (const float*)d_in[2];
    const float* b_self   = (const float*)d_in[3];
    const float* W_neigh  = (const float*)d_in[4];
    const float* b_neigh  = (const float*)d_in[5];
    float*       out      = (float*)d_out;

    static void* agg_ptr = nullptr;
    static void* deg_ptr = nullptr;
    if (!agg_ptr) {
        cudaGetSymbolAddress(&agg_ptr, g_agg);
        cudaGetSymbolAddress(&deg_ptr, g_deg);
    }

    cudaMemsetAsync(agg_ptr, 0, (size_t)N_NODES * DIM * sizeof(float));
    cudaMemsetAsync(deg_ptr, 0, (size_t)N_NODES * sizeof(float));

    {
        long long total = (long long)N_EDGES * 24;
        int blocks = (int)((total + 255) / 256);
        scatter_kernel<<<blocks, 256>>>(x, ei);
    }

    gemm_kernel<<<GEMM_BLOCKS, GT>>>(x, W_self, b_self, W_neigh, b_neigh, out);
}

// round 12
// speedup vs baseline: 1.0704x; 1.0704x over previous
#include <cuda_runtime.h>

#define N_NODES 50000
#define N_EDGES 800000
#define DIM 96
#define CAP 64   // bucket capacity per node (avg degree 16; Poisson tail safe)

typedef unsigned long long ull;

// ---------------------------------------------------------------------------
// Scratch (__device__ globals per allocation-free rule)
// ---------------------------------------------------------------------------
__device__ __align__(128) float g_agg[N_NODES * DIM];   // raw neighbor sums
__device__ int g_cnt[N_NODES];                          // degree
__device__ int g_bucket[N_NODES * CAP];                 // src ids, 12.8 MB
__device__ int g_novf;                                  // overflow count
__device__ int g_ovf[N_EDGES * 2];                      // overflow (src,dst)

// ---------------------------------------------------------------------------
// Fill: bucket the edges by destination. No prefix sum needed.
// ---------------------------------------------------------------------------
__global__ void fill_kernel(const int* __restrict__ ei) {
    int e = blockIdx.x * blockDim.x + threadIdx.x;
    if (e >= N_EDGES) return;
    int src = __ldg(&ei[e]);
    int dst = __ldg(&ei[N_EDGES + e]);
    int slot = atomicAdd(&g_cnt[dst], 1);
    if (slot < CAP) {
        g_bucket[dst * CAP + slot] = src;
    } else {
        int o = atomicAdd(&g_novf, 1);
        g_ovf[2 * o + 0] = src;
        g_ovf[2 * o + 1] = dst;
    }
}

// ---------------------------------------------------------------------------
// Gather: 96 threads/node (2 nodes per 192-thread block). Thread j sums
// feature j over bucketed neighbors; writes RAW sum (GEMM normalizes).
// ---------------------------------------------------------------------------
__global__ void gather_kernel(const float* __restrict__ x) {
    int node = blockIdx.x * 2 + (threadIdx.x / 96);
    int j = threadIdx.x % 96;
    if (node >= N_NODES) return;

    int deg = g_cnt[node];
    int n = (deg < CAP) ? deg : CAP;
    const int* __restrict__ b = g_bucket + (size_t)node * CAP;

    float acc = 0.0f;
    int s = 0;
    for (; s + 4 <= n; s += 4) {
        int s0 = __ldg(&b[s + 0]);
        int s1 = __ldg(&b[s + 1]);
        int s2 = __ldg(&b[s + 2]);
        int s3 = __ldg(&b[s + 3]);
        float a0 = __ldg(&x[(size_t)s0 * DIM + j]);
        float a1 = __ldg(&x[(size_t)s1 * DIM + j]);
        float a2 = __ldg(&x[(size_t)s2 * DIM + j]);
        float a3 = __ldg(&x[(size_t)s3 * DIM + j]);
        acc += a0 + a1 + a2 + a3;
    }
    for (; s < n; s++) {
        int s0 = __ldg(&b[s]);
        acc += __ldg(&x[(size_t)s0 * DIM + j]);
    }
    g_agg[(size_t)node * DIM + j] = acc;
}

// ---------------------------------------------------------------------------
// Overflow: atomically add x[src] into g_agg for edges beyond CAP.
// Runs AFTER gather (stream order). Usually zero work.
// ---------------------------------------------------------------------------
__global__ void ovf_kernel(const float* __restrict__ x) {
    int n = g_novf;
    int total = n * 24;
    int stride = gridDim.x * blockDim.x;
    for (int t = blockIdx.x * blockDim.x + threadIdx.x; t < total; t += stride) {
        int e = t / 24, c = t % 24;
        int src = g_ovf[2 * e + 0];
        int dst = g_ovf[2 * e + 1];
        float4 v = ((const float4*)(x + (size_t)src * DIM))[c];
        float* p = g_agg + (size_t)dst * DIM + c * 4;
        asm volatile("red.global.add.v4.f32 [%0], {%1,%2,%3,%4};"
                     :: "l"(p), "f"(v.x), "f"(v.y), "f"(v.z), "f"(v.w)
                     : "memory");
    }
}

// ---------------------------------------------------------------------------
// GEMM half (round-7 config): out(+)= A @ W^T + bias. BM=64, BN=96, K=96,
// 128 threads, TM=8 x TN=6, packed fma.rn.f32x2.
// NEIGH: A = g_agg scaled by 1/max(cnt,1); accumulate into out.
// ---------------------------------------------------------------------------
#define BM 64
#define BN 96
#define TM 8
#define TN 6
#define GT 128
#define GEMM_BLOCKS ((N_NODES + BM - 1) / BM)   // 782
#define APITCH 100
#define BPITCH 49

__device__ __forceinline__ void ffma2(ull& d, ull a, ull b) {
    asm("fma.rn.f32x2 %0, %1, %2, %0;" : "+l"(d) : "l"(a), "l"(b));
}

template <bool NEIGH>
__global__ void gemm_half(const float* __restrict__ A,
                          const float* __restrict__ W,
                          const float* __restrict__ bias,
                          float* __restrict__ out) {
    __shared__ __align__(16) float  sA[BM][APITCH];
    __shared__ __align__(16) float2 sB[BN][BPITCH];
    __shared__ float sInv[BM];

    const int tid = threadIdx.x;
    const int tx = tid % (BN / TN);     // 0..15 column group
    const int ty = tid / (BN / TN);     // 0..7  row group
    const int rowBase = blockIdx.x * BM;

    if (NEIGH) {
        if (tid < BM) {
            int row = rowBase + tid;
            int d = (row < N_NODES) ? g_cnt[row] : 1;
            sInv[tid] = 1.0f / (float)((d > 1) ? d : 1);
        }
        __syncthreads();
    }

    #pragma unroll
    for (int it = 0; it < 12; it++) {
        int idx = tid + it * GT;
        int m = idx / 24, q = idx % 24;
        int row = rowBase + m;
        float4 v = make_float4(0.f, 0.f, 0.f, 0.f);
        if (row < N_NODES) {
            v = ((const float4*)(A + (size_t)row * DIM))[q];
            if (NEIGH) {
                float inv = sInv[m];
                v.x *= inv; v.y *= inv; v.z *= inv; v.w *= inv;
            }
        }
        ((float4*)&sA[m][0])[q] = v;
    }
    #pragma unroll
    for (int it = 0; it < 18; it++) {
        int idx = tid + it * GT;
        int j = idx / 24, q = idx % 24;
        float4 v = *(const float4*)(W + (size_t)j * DIM + q * 4);
        sB[j][2 * q + 0] = make_float2(v.x, v.y);
        sB[j][2 * q + 1] = make_float2(v.z, v.w);
    }
    __syncthreads();

    ull acc2[TM][TN];
    #pragma unroll
    for (int i = 0; i < TM; i++)
        #pragma unroll
        for (int j = 0; j < TN; j++) acc2[i][j] = 0ULL;

    #pragma unroll 4
    for (int kp = 0; kp < DIM / 2; kp++) {
        ull a2[TM], b2[TN];
        #pragma unroll
        for (int i = 0; i < TM; i++)
            a2[i] = *(const ull*)&sA[ty * TM + i][2 * kp];
        #pragma unroll
        for (int j = 0; j < TN; j++)
            b2[j] = *(const ull*)&sB[tx * TN + j][kp];
        #pragma unroll
        for (int i = 0; i < TM; i++)
            #pragma unroll
            for (int j = 0; j < TN; j++)
                ffma2(acc2[i][j], a2[i], b2[j]);
    }

    const int colBase = tx * TN;
    #pragma unroll
    for (int i = 0; i < TM; i++) {
        int row = rowBase + ty * TM + i;
        if (row < N_NODES) {
            float r[TN];
            #pragma unroll
            for (int j = 0; j < TN; j++) {
                ull u = acc2[i][j];
                r[j] = __uint_as_float((unsigned)(u & 0xffffffffu)) +
                       __uint_as_float((unsigned)(u >> 32));
            }
            float* op = out + (size_t)row * DIM + colBase;
            #pragma unroll
            for (int j2 = 0; j2 < TN / 2; j2++) {
                float2 v;
                v.x = r[2 * j2 + 0] + bias[colBase + 2 * j2 + 0];
                v.y = r[2 * j2 + 1] + bias[colBase + 2 * j2 + 1];
                if (NEIGH) {
                    float2 prev = *(float2*)(op + 2 * j2);
                    v.x += prev.x;
                    v.y += prev.y;
                }
                *(float2*)(op + 2 * j2) = v;
            }
        }
    }
}

// ---------------------------------------------------------------------------
extern "C" void kernel_launch(void* const* d_in, const int* in_sizes, int n_in,
                              void* d_out, int out_size) {
    const float* x        = (const float*)d_in[0];
    const int*   ei       = (const int*)d_in[1];
    const float* W_self   = (const float*)d_in[2];
    const float* b_self   = (const float*)d_in[3];
    const float* W_neigh  = (const float*)d_in[4];
    const float* b_neigh  = (const float*)d_in[5];
    float*       out      = (float*)d_out;

    static void* cnt_ptr = nullptr;
    static void* novf_ptr = nullptr;
    static float* agg_f = nullptr;
    if (!cnt_ptr) {
        cudaGetSymbolAddress(&cnt_ptr, g_cnt);
        cudaGetSymbolAddress(&novf_ptr, g_novf);
        void* p; cudaGetSymbolAddress(&p, g_agg);
        agg_f = (float*)p;
    }

    cudaMemsetAsync(cnt_ptr, 0, (size_t)N_NODES * sizeof(int));
    cudaMemsetAsync(novf_ptr, 0, sizeof(int));

    fill_kernel<<<(N_EDGES + 255) / 256, 256>>>(ei);
    gather_kernel<<<(N_NODES + 1) / 2, 192>>>(x);
    ovf_kernel<<<64, 256>>>(x);

    gemm_half<false><<<GEMM_BLOCKS, GT>>>(x, W_self, b_self, out);
    gemm_half<true><<<GEMM_BLOCKS, GT>>>(agg_f, W_neigh, b_neigh, out);
}

// round 13
// speedup vs baseline: 1.1456x; 1.0703x over previous
#include <cuda_runtime.h>
#include <cuda_fp16.h>

#define N_NODES 50000
#define N_EDGES 800000
#define DIM 96
#define CAP 64   // bucket capacity per node (avg degree 16)

typedef unsigned long long ull;

// ---------------------------------------------------------------------------
// Scratch (__device__ globals per allocation-free rule)
// ---------------------------------------------------------------------------
__device__ __align__(128) float g_agg[N_NODES * DIM];   // raw neighbor sums
__device__ __align__(128) __half g_xh[N_NODES * DIM];   // fp16 mirror of x
__device__ int g_cnt[N_NODES];                          // degree
__device__ int g_bucket[N_NODES * CAP];                 // src ids, 12.8 MB
__device__ int g_novf;                                  // overflow count
__device__ int g_ovf[N_EDGES * 2];                      // overflow (src,dst)

// ---------------------------------------------------------------------------
// Convert x -> fp16 mirror (half2-vectorized).
// ---------------------------------------------------------------------------
__global__ void convert_kernel(const float* __restrict__ x) {
    int t = blockIdx.x * blockDim.x + threadIdx.x;
    const int total = N_NODES * DIM / 2;
    if (t < total) {
        float2 v = ((const float2*)x)[t];
        ((__half2*)g_xh)[t] = __floats2half2_rn(v.x, v.y);
    }
}

// ---------------------------------------------------------------------------
// Fill: bucket the edges by destination. No prefix sum needed.
// ---------------------------------------------------------------------------
__global__ void fill_kernel(const int* __restrict__ ei) {
    int e = blockIdx.x * blockDim.x + threadIdx.x;
    if (e >= N_EDGES) return;
    int src = __ldg(&ei[e]);
    int dst = __ldg(&ei[N_EDGES + e]);
    int slot = atomicAdd(&g_cnt[dst], 1);
    if (slot < CAP) {
        g_bucket[dst * CAP + slot] = src;
    } else {
        int o = atomicAdd(&g_novf, 1);
        g_ovf[2 * o + 0] = src;
        g_ovf[2 * o + 1] = dst;
    }
}

// ---------------------------------------------------------------------------
// Gather (fp16 reads, fp32 accumulation): 48 threads/node, thread owns a
// feature pair (half2). 4 nodes per 192-thread block.
// Writes RAW sums; the neigh-GEMM normalizes by 1/max(deg,1).
// ---------------------------------------------------------------------------
__global__ void gather_kernel() {
    int node = blockIdx.x * 4 + (threadIdx.x / 48);
    int j2 = threadIdx.x % 48;          // half2 index 0..47
    if (node >= N_NODES) return;

    int deg = g_cnt[node];
    int n = (deg < CAP) ? deg : CAP;
    const int* __restrict__ b = g_bucket + (size_t)node * CAP;
    const __half2* __restrict__ xh2 = (const __half2*)g_xh;

    float2 acc = make_float2(0.0f, 0.0f);
    int s = 0;
    for (; s + 4 <= n; s += 4) {
        int s0 = __ldg(&b[s + 0]);
        int s1 = __ldg(&b[s + 1]);
        int s2 = __ldg(&b[s + 2]);
        int s3 = __ldg(&b[s + 3]);
        float2 a0 = __half22float2(xh2[(size_t)s0 * 48 + j2]);
        float2 a1 = __half22float2(xh2[(size_t)s1 * 48 + j2]);
        float2 a2 = __half22float2(xh2[(size_t)s2 * 48 + j2]);
        float2 a3 = __half22float2(xh2[(size_t)s3 * 48 + j2]);
        acc.x += (a0.x + a1.x) + (a2.x + a3.x);
        acc.y += (a0.y + a1.y) + (a2.y + a3.y);
    }
    for (; s < n; s++) {
        int s0 = __ldg(&b[s]);
        float2 a = __half22float2(xh2[(size_t)s0 * 48 + j2]);
        acc.x += a.x;
        acc.y += a.y;
    }
    ((float2*)g_agg)[(size_t)node * 48 + j2] = acc;
}

// ---------------------------------------------------------------------------
// Overflow: atomically add x[src] (fp32) into g_agg for edges beyond CAP.
// Runs AFTER gather. Usually zero work.
// ---------------------------------------------------------------------------
__global__ void ovf_kernel(const float* __restrict__ x) {
    int n = g_novf;
    int total = n * 24;
    int stride = gridDim.x * blockDim.x;
    for (int t = blockIdx.x * blockDim.x + threadIdx.x; t < total; t += stride) {
        int e = t / 24, c = t % 24;
        int src = g_ovf[2 * e + 0];
        int dst = g_ovf[2 * e + 1];
        float4 v = ((const float4*)(x + (size_t)src * DIM))[c];
        float* p = g_agg + (size_t)dst * DIM + c * 4;
        asm volatile("red.global.add.v4.f32 [%0], {%1,%2,%3,%4};"
                     :: "l"(p), "f"(v.x), "f"(v.y), "f"(v.z), "f"(v.w)
                     : "memory");
    }
}

// ---------------------------------------------------------------------------
// GEMM half (best-known config): out(+)= A @ W^T + bias. BM=64, BN=96, K=96,
// 128 threads, TM=8 x TN=6, packed fma.rn.f32x2.
// NEIGH: A = g_agg scaled by 1/max(cnt,1); accumulate into out.
// ---------------------------------------------------------------------------
#define BM 64
#define BN 96
#define TM 8
#define TN 6
#define GT 128
#define GEMM_BLOCKS ((N_NODES + BM - 1) / BM)   // 782
#define APITCH 100
#define BPITCH 49

__device__ __forceinline__ void ffma2(ull& d, ull a, ull b) {
    asm("fma.rn.f32x2 %0, %1, %2, %0;" : "+l"(d) : "l"(a), "l"(b));
}

template <bool NEIGH>
__global__ void gemm_half(const float* __restrict__ A,
                          const float* __restrict__ W,
                          const float* __restrict__ bias,
                          float* __restrict__ out) {
    __shared__ __align__(16) float  sA[BM][APITCH];
    __shared__ __align__(16) float2 sB[BN][BPITCH];
    __shared__ float sInv[BM];

    const int tid = threadIdx.x;
    const int tx = tid % (BN / TN);     // 0..15 column group
    const int ty = tid / (BN / TN);     // 0..7  row group
    const int rowBase = blockIdx.x * BM;

    if (NEIGH) {
        if (tid < BM) {
            int row = rowBase + tid;
            int d = (row < N_NODES) ? g_cnt[row] : 1;
            sInv[tid] = 1.0f / (float)((d > 1) ? d : 1);
        }
        __syncthreads();
    }

    #pragma unroll
    for (int it = 0; it < 12; it++) {
        int idx = tid + it * GT;
        int m = idx / 24, q = idx % 24;
        int row = rowBase + m;
        float4 v = make_float4(0.f, 0.f, 0.f, 0.f);
        if (row < N_NODES) {
            v = ((const float4*)(A + (size_t)row * DIM))[q];
            if (NEIGH) {
                float inv = sInv[m];
                v.x *= inv; v.y *= inv; v.z *= inv; v.w *= inv;
            }
        }
        ((float4*)&sA[m][0])[q] = v;
    }
    #pragma unroll
    for (int it = 0; it < 18; it++) {
        int idx = tid + it * GT;
        int j = idx / 24, q = idx % 24;
        float4 v = *(const float4*)(W + (size_t)j * DIM + q * 4);
        sB[j][2 * q + 0] = make_float2(v.x, v.y);
        sB[j][2 * q + 1] = make_float2(v.z, v.w);
    }
    __syncthreads();

    ull acc2[TM][TN];
    #pragma unroll
    for (int i = 0; i < TM; i++)
        #pragma unroll
        for (int j = 0; j < TN; j++) acc2[i][j] = 0ULL;

    #pragma unroll 4
    for (int kp = 0; kp < DIM / 2; kp++) {
        ull a2[TM], b2[TN];
        #pragma unroll
        for (int i = 0; i < TM; i++)
            a2[i] = *(const ull*)&sA[ty * TM + i][2 * kp];
        #pragma unroll
        for (int j = 0; j < TN; j++)
            b2[j] = *(const ull*)&sB[tx * TN + j][kp];
        #pragma unroll
        for (int i = 0; i < TM; i++)
            #pragma unroll
            for (int j = 0; j < TN; j++)
                ffma2(acc2[i][j], a2[i], b2[j]);
    }

    const int colBase = tx * TN;
    #pragma unroll
    for (int i = 0; i < TM; i++) {
        int row = rowBase + ty * TM + i;
        if (row < N_NODES) {
            float r[TN];
            #pragma unroll
            for (int j = 0; j < TN; j++) {
                ull u = acc2[i][j];
                r[j] = __uint_as_float((unsigned)(u & 0xffffffffu)) +
                       __uint_as_float((unsigned)(u >> 32));
            }
            float* op = out + (size_t)row * DIM + colBase;
            #pragma unroll
            for (int j2 = 0; j2 < TN / 2; j2++) {
                float2 v;
                v.x = r[2 * j2 + 0] + bias[colBase + 2 * j2 + 0];
                v.y = r[2 * j2 + 1] + bias[colBase + 2 * j2 + 1];
                if (NEIGH) {
                    float2 prev = *(float2*)(op + 2 * j2);
                    v.x += prev.x;
                    v.y += prev.y;
                }
                *(float2*)(op + 2 * j2) = v;
            }
        }
    }
}

// ---------------------------------------------------------------------------
extern "C" void kernel_launch(void* const* d_in, const int* in_sizes, int n_in,
                              void* d_out, int out_size) {
    const float* x        = (const float*)d_in[0];
    const int*   ei       = (const int*)d_in[1];
    const float* W_self   = (const float*)d_in[2];
    const float* b_self   = (const float*)d_in[3];
    const float* W_neigh  = (const float*)d_in[4];
    const float* b_neigh  = (const float*)d_in[5];
    float*       out      = (float*)d_out;

    static void* cnt_ptr = nullptr;
    static void* novf_ptr = nullptr;
    static float* agg_f = nullptr;
    if (!cnt_ptr) {
        cudaGetSymbolAddress(&cnt_ptr, g_cnt);
        cudaGetSymbolAddress(&novf_ptr, g_novf);
        void* p; cudaGetSymbolAddress(&p, g_agg);
        agg_f = (float*)p;
    }

    cudaMemsetAsync(cnt_ptr, 0, (size_t)N_NODES * sizeof(int));
    cudaMemsetAsync(novf_ptr, 0, sizeof(int));

    convert_kernel<<<(N_NODES * DIM / 2 + 255) / 256, 256>>>(x);
    fill_kernel<<<(N_EDGES + 255) / 256, 256>>>(ei);
    gather_kernel<<<(N_NODES + 3) / 4, 192>>>();
    ovf_kernel<<<64, 256>>>(x);

    gemm_half<false><<<GEMM_BLOCKS, GT>>>(x, W_self, b_self, out);
    gemm_half<true><<<GEMM_BLOCKS, GT>>>(agg_f, W_neigh, b_neigh, out);
}

// round 14
// speedup vs baseline: 1.6195x; 1.4137x over previous
#include <cuda_runtime.h>
#include <cuda_fp16.h>
#include <cstdint>

#define N_NODES 50000
#define N_EDGES 800000
#define DIM 96
#define KTOT 192
#define CAP 64   // bucket capacity per node (avg degree 16)

// ---------------------------------------------------------------------------
// Scratch (__device__ globals per allocation-free rule)
// ---------------------------------------------------------------------------
__device__ __align__(128) __half g_ah[N_NODES * KTOT];  // [xh | mean_h], 19.2MB
__device__ __align__(128) __half g_wh[DIM * KTOT];      // B fp16 [n][k], 36.9KB
__device__ __align__(128) float g_agg[N_NODES * DIM];   // raw fp32 sums
__device__ int g_cnt[N_NODES];
__device__ int g_bucket[N_NODES * CAP];                 // 12.8 MB
__device__ int g_novf;
__device__ int g_ovf[N_EDGES * 2];

// ---------------------------------------------------------------------------
// Convert x -> fp16 into first 96 cols of g_ah (stride 192 halves).
// ---------------------------------------------------------------------------
__global__ void convert_x_kernel(const float* __restrict__ x) {
    int t = blockIdx.x * blockDim.x + threadIdx.x;
    const int total = N_NODES * 48;         // half2 count
    if (t < total) {
        int row = t / 48, j2 = t % 48;
        float2 v = ((const float2*)x)[t];
        ((__half2*)g_ah)[(size_t)row * 96 + j2] = __floats2half2_rn(v.x, v.y);
    }
}

// Convert [Ws | Wn] -> g_wh[j][k], k = 0..191 (fp16).
__global__ void convert_w_kernel(const float* __restrict__ Ws,
                                 const float* __restrict__ Wn) {
    int t = blockIdx.x * blockDim.x + threadIdx.x;
    const int total = DIM * 48;
    if (t < total) {
        int j = t / 48, kp = t % 48;
        float2 a = ((const float2*)Ws)[j * 48 + kp];
        float2 b = ((const float2*)Wn)[j * 48 + kp];
        ((__half2*)g_wh)[j * 96 + kp]      = __floats2half2_rn(a.x, a.y);
        ((__half2*)g_wh)[j * 96 + 48 + kp] = __floats2half2_rn(b.x, b.y);
    }
}

// ---------------------------------------------------------------------------
// Fill: bucket the edges by destination.
// ---------------------------------------------------------------------------
__global__ void fill_kernel(const int* __restrict__ ei) {
    int e = blockIdx.x * blockDim.x + threadIdx.x;
    if (e >= N_EDGES) return;
    int src = __ldg(&ei[e]);
    int dst = __ldg(&ei[N_EDGES + e]);
    int slot = atomicAdd(&g_cnt[dst], 1);
    if (slot < CAP) {
        g_bucket[dst * CAP + slot] = src;
    } else {
        int o = atomicAdd(&g_novf, 1);
        g_ovf[2 * o + 0] = src;
        g_ovf[2 * o + 1] = dst;
    }
}

// ---------------------------------------------------------------------------
// Gather: 48 threads/node (4 nodes per 192-thread block), fp16 reads from
// g_ah's x-half, fp32 accumulation; writes RAW sums to g_agg.
// ---------------------------------------------------------------------------
__global__ void gather_kernel() {
    int node = blockIdx.x * 4 + (threadIdx.x / 48);
    int j2 = threadIdx.x % 48;
    if (node >= N_NODES) return;

    int deg = g_cnt[node];
    int n = (deg < CAP) ? deg : CAP;
    const int* __restrict__ b = g_bucket + (size_t)node * CAP;
    const __half2* __restrict__ xh2 = (const __half2*)g_ah;   // row stride 96

    float2 acc = make_float2(0.0f, 0.0f);
    int s = 0;
    for (; s + 4 <= n; s += 4) {
        int s0 = __ldg(&b[s + 0]);
        int s1 = __ldg(&b[s + 1]);
        int s2 = __ldg(&b[s + 2]);
        int s3 = __ldg(&b[s + 3]);
        float2 a0 = __half22float2(xh2[(size_t)s0 * 96 + j2]);
        float2 a1 = __half22float2(xh2[(size_t)s1 * 96 + j2]);
        float2 a2 = __half22float2(xh2[(size_t)s2 * 96 + j2]);
        float2 a3 = __half22float2(xh2[(size_t)s3 * 96 + j2]);
        acc.x += (a0.x + a1.x) + (a2.x + a3.x);
        acc.y += (a0.y + a1.y) + (a2.y + a3.y);
    }
    for (; s < n; s++) {
        int s0 = __ldg(&b[s]);
        float2 a = __half22float2(xh2[(size_t)s0 * 96 + j2]);
        acc.x += a.x;
        acc.y += a.y;
    }
    ((float2*)g_agg)[(size_t)node * 48 + j2] = acc;
}

// ---------------------------------------------------------------------------
// Overflow: fp32 red-add of x[src] into g_agg (before normalize).
// ---------------------------------------------------------------------------
__global__ void ovf_kernel(const float* __restrict__ x) {
    int n = g_novf;
    int total = n * 24;
    int stride = gridDim.x * blockDim.x;
    for (int t = blockIdx.x * blockDim.x + threadIdx.x; t < total; t += stride) {
        int e = t / 24, c = t % 24;
        int src = g_ovf[2 * e + 0];
        int dst = g_ovf[2 * e + 1];
        float4 v = ((const float4*)(x + (size_t)src * DIM))[c];
        float* p = g_agg + (size_t)dst * DIM + c * 4;
        asm volatile("red.global.add.v4.f32 [%0], {%1,%2,%3,%4};"
                     :: "l"(p), "f"(v.x), "f"(v.y), "f"(v.z), "f"(v.w)
                     : "memory");
    }
}

// ---------------------------------------------------------------------------
// Normalize raw sums by 1/max(deg,1), convert to fp16 into g_ah cols 96..191.
// ---------------------------------------------------------------------------
__global__ void normalize_kernel() {
    int t = blockIdx.x * blockDim.x + threadIdx.x;
    const int total = N_NODES * 48;
    if (t < total) {
        int row = t / 48, j2 = t % 48;
        int d = g_cnt[row];
        float inv = 1.0f / (float)((d > 1) ? d : 1);
        float2 v = ((const float2*)g_agg)[t];
        ((__half2*)g_ah)[(size_t)row * 96 + 48 + j2] =
            __floats2half2_rn(v.x * inv, v.y * inv);
    }
}

// ---------------------------------------------------------------------------
// HMMA GEMM: out[50000,96] = g_ah[50000,192] @ g_wh[96,192]^T + (bs+bn)
// BM=128 rows/block, 4 warps; warp = 32 rows x 96 cols = 2x12 m16n8k16 tiles.
// Smem pitch 200 halves (400B) -> conflict-free ldmatrix.
// ---------------------------------------------------------------------------
#define HBM 128
#define HPITCH 200
#define HMMA_THREADS 128
#define HMMA_BLOCKS ((N_NODES + HBM - 1) / HBM)   // 391
#define HMMA_SMEM ((HBM + DIM) * HPITCH * 2)      // 89600 bytes

__device__ __forceinline__ uint32_t smem_u32(const void* p) {
    return (uint32_t)__cvta_generic_to_shared(p);
}
__device__ __forceinline__ void ldsm_x4(uint32_t& r0, uint32_t& r1,
                                        uint32_t& r2, uint32_t& r3,
                                        uint32_t addr) {
    asm volatile("ldmatrix.sync.aligned.m8n8.x4.shared.b16 {%0,%1,%2,%3}, [%4];"
                 : "=r"(r0), "=r"(r1), "=r"(r2), "=r"(r3) : "r"(addr));
}
__device__ __forceinline__ void mma16816(float* d, const uint32_t* a,
                                         const uint32_t* b) {
    asm volatile(
        "mma.sync.aligned.m16n8k16.row.col.f32.f16.f16.f32 "
        "{%0,%1,%2,%3}, {%4,%5,%6,%7}, {%8,%9}, {%0,%1,%2,%3};"
        : "+f"(d[0]), "+f"(d[1]), "+f"(d[2]), "+f"(d[3])
        : "r"(a[0]), "r"(a[1]), "r"(a[2]), "r"(a[3]), "r"(b[0]), "r"(b[1]));
}

__global__ __launch_bounds__(HMMA_THREADS)
void hmma_kernel(const float* __restrict__ bs, const float* __restrict__ bn,
                 float* __restrict__ out) {
    extern __shared__ __half hsm[];
    __half* sA = hsm;                      // [HBM][HPITCH]
    __half* sB = hsm + HBM * HPITCH;       // [DIM][HPITCH]
    __shared__ float sBias[DIM];

    const int tid = threadIdx.x;
    const int warp = tid >> 5;
    const int lane = tid & 31;
    const int rowBase = blockIdx.x * HBM;

    if (tid < DIM) sBias[tid] = bs[tid] + bn[tid];

    // Load A: 128 rows x 192 halves = 24 uint4/row, 3072 total (24/thread).
    #pragma unroll
    for (int it = 0; it < 24; it++) {
        int idx = it * HMMA_THREADS + tid;
        int m = idx / 24, q = idx % 24;
        int row = rowBase + m;
        uint4 v = make_uint4(0u, 0u, 0u, 0u);
        if (row < N_NODES)
            v = ((const uint4*)(g_ah + (size_t)row * KTOT))[q];
        *(uint4*)&sA[m * HPITCH + q * 8] = v;
    }
    // Load B: 96 rows x 24 uint4 = 2304 (18/thread).
    #pragma unroll
    for (int it = 0; it < 18; it++) {
        int idx = it * HMMA_THREADS + tid;
        int j = idx / 24, q = idx % 24;
        *(uint4*)&sB[j * HPITCH + q * 8] = ((const uint4*)(g_wh + j * KTOT))[q];
    }
    __syncthreads();

    float acc[2][12][4];
    #pragma unroll
    for (int mt = 0; mt < 2; mt++)
        #pragma unroll
        for (int nt = 0; nt < 12; nt++)
            #pragma unroll
            for (int i = 0; i < 4; i++) acc[mt][nt][i] = 0.0f;

    const int mrow0 = warp * 32;

    #pragma unroll 3
    for (int k16 = 0; k16 < KTOT / 16; k16++) {
        int k0 = k16 * 16;
        uint32_t a[2][4];
        #pragma unroll
        for (int mt = 0; mt < 2; mt++) {
            uint32_t addr = smem_u32(
                &sA[(mrow0 + mt * 16 + (lane & 15)) * HPITCH +
                    k0 + ((lane >> 4) << 3)]);
            ldsm_x4(a[mt][0], a[mt][1], a[mt][2], a[mt][3], addr);
        }
        uint32_t b[12][2];
        #pragma unroll
        for (int np = 0; np < 6; np++) {
            int n0 = np * 16;
            int nrow = n0 + ((lane >> 4) << 3) + (lane & 7);
            int kcol = k0 + (((lane >> 3) & 1) << 3);
            uint32_t addr = smem_u32(&sB[nrow * HPITCH + kcol]);
            uint32_t r0, r1, r2, r3;
            ldsm_x4(r0, r1, r2, r3, addr);
            b[2 * np + 0][0] = r0; b[2 * np + 0][1] = r1;
            b[2 * np + 1][0] = r2; b[2 * np + 1][1] = r3;
        }
        #pragma unroll
        for (int mt = 0; mt < 2; mt++)
            #pragma unroll
            for (int nt = 0; nt < 12; nt++)
                mma16816(acc[mt][nt], a[mt], b[nt]);
    }

    // Epilogue: D layout m16n8 — lane l: rows l/4 and l/4+8, cols (l%4)*2,+1.
    #pragma unroll
    for (int mt = 0; mt < 2; mt++) {
        int r0 = rowBase + mrow0 + mt * 16 + (lane >> 2);
        #pragma unroll
        for (int nt = 0; nt < 12; nt++) {
            int c = nt * 8 + (lane & 3) * 2;
            float bx = sBias[c], by = sBias[c + 1];
            if (r0 < N_NODES) {
                float2 v0 = make_float2(acc[mt][nt][0] + bx,
                                        acc[mt][nt][1] + by);
                *(float2*)(out + (size_t)r0 * DIM + c) = v0;
            }
            int r1 = r0 + 8;
            if (r1 < N_NODES) {
                float2 v1 = make_float2(acc[mt][nt][2] + bx,
                                        acc[mt][nt][3] + by);
                *(float2*)(out + (size_t)r1 * DIM + c) = v1;
            }
        }
    }
}

// ---------------------------------------------------------------------------
extern "C" void kernel_launch(void* const* d_in, const int* in_sizes, int n_in,
                              void* d_out, int out_size) {
    const float* x        = (const float*)d_in[0];
    const int*   ei       = (const int*)d_in[1];
    const float* W_self   = (const float*)d_in[2];
    const float* b_self   = (const float*)d_in[3];
    const float* W_neigh  = (const float*)d_in[4];
    const float* b_neigh  = (const float*)d_in[5];
    float*       out      = (float*)d_out;

    static void* cnt_ptr = nullptr;
    static void* novf_ptr = nullptr;
    if (!cnt_ptr) {
        cudaGetSymbolAddress(&cnt_ptr, g_cnt);
        cudaGetSymbolAddress(&novf_ptr, g_novf);
        cudaFuncSetAttribute(hmma_kernel,
                             cudaFuncAttributeMaxDynamicSharedMemorySize,
                             HMMA_SMEM);
    }

    cudaMemsetAsync(cnt_ptr, 0, (size_t)N_NODES * sizeof(int));
    cudaMemsetAsync(novf_ptr, 0, sizeof(int));

    convert_x_kernel<<<(N_NODES * 48 + 255) / 256, 256>>>(x);
    convert_w_kernel<<<(DIM * 48 + 255) / 256, 256>>>(W_self, W_neigh);
    fill_kernel<<<(N_EDGES + 255) / 256, 256>>>(ei);
    gather_kernel<<<(N_NODES + 3) / 4, 192>>>();
    ovf_kernel<<<32, 256>>>(x);
    normalize_kernel<<<(N_NODES * 48 + 255) / 256, 256>>>();
    hmma_kernel<<<HMMA_BLOCKS, HMMA_THREADS, HMMA_SMEM>>>(b_self, b_neigh, out);
}

// round 15
// speedup vs baseline: 2.1117x; 1.3039x over previous
#include <cuda_runtime.h>
#include <cuda_fp16.h>
#include <cstdint>

#define N_NODES 50000
#define N_EDGES 800000
#define DIM 96
#define KTOT 192
#define CAP 64   // bucket capacity per node (avg degree 16)

// ---------------------------------------------------------------------------
// Scratch (__device__ globals per allocation-free rule)
// ---------------------------------------------------------------------------
__device__ __align__(128) __half g_ah[N_NODES * KTOT];  // [xh | mean_h], 19.2MB
__device__ __align__(128) __half g_wh[DIM * KTOT];      // B fp16 [n][k]
__device__ __align__(128) float g_agg[N_NODES * DIM];   // raw sums (ovf rows)
__device__ int g_cnt[N_NODES];
__device__ int g_bucket[N_NODES * CAP];                 // 12.8 MB
__device__ int g_novf;
__device__ int g_ovf[N_EDGES * 2];

// ---------------------------------------------------------------------------
// Convert x -> fp16 (first 96 cols of g_ah) and [Ws|Wn] -> g_wh, one kernel.
// ---------------------------------------------------------------------------
#define NXH2 (N_NODES * 48)       // half2 items for x
#define NWH2 (DIM * 48)           // half2 items per weight matrix

__global__ void convert_kernel(const float* __restrict__ x,
                               const float* __restrict__ Ws,
                               const float* __restrict__ Wn) {
    int t = blockIdx.x * blockDim.x + threadIdx.x;
    if (t < NXH2) {
        int row = t / 48, j2 = t % 48;
        float2 v = ((const float2*)x)[t];
        ((__half2*)g_ah)[row * 96 + j2] = __floats2half2_rn(v.x, v.y);
    } else if (t < NXH2 + NWH2) {
        int u = t - NXH2;
        int j = u / 48, kp = u % 48;
        float2 a = ((const float2*)Ws)[u];
        float2 b = ((const float2*)Wn)[u];
        ((__half2*)g_wh)[j * 96 + kp]      = __floats2half2_rn(a.x, a.y);
        ((__half2*)g_wh)[j * 96 + 48 + kp] = __floats2half2_rn(b.x, b.y);
    }
}

// ---------------------------------------------------------------------------
// Fill: bucket the edges by destination.
// ---------------------------------------------------------------------------
__global__ void fill_kernel(const int* __restrict__ ei) {
    int e = blockIdx.x * blockDim.x + threadIdx.x;
    if (e >= N_EDGES) return;
    int src = __ldg(&ei[e]);
    int dst = __ldg(&ei[N_EDGES + e]);
    int slot = atomicAdd(&g_cnt[dst], 1);
    if (slot < CAP) {
        g_bucket[dst * CAP + slot] = src;
    } else {
        int o = atomicAdd(&g_novf, 1);
        g_ovf[2 * o + 0] = src;
        g_ovf[2 * o + 1] = dst;
    }
}

// ---------------------------------------------------------------------------
// Gather: 24 threads/node (8 nodes per 192-thread block). Thread owns 4
// features; per neighbor one uint2 (4 fp16) load; bucket read via int4.
// Fast path (deg<=CAP): writes normalized fp16 mean directly to g_ah.
// Overflow rows: write raw fp32 sums to g_agg (fixed by ovf_fix_kernel).
// ---------------------------------------------------------------------------
__global__ void gather_kernel() {
    int node = blockIdx.x * 8 + (threadIdx.x / 24);
    int j4 = threadIdx.x % 24;          // uint2 (4-half) index 0..23
    if (node >= N_NODES) return;

    int deg = g_cnt[node];
    int n = (deg < CAP) ? deg : CAP;
    const int* __restrict__ b = g_bucket + node * CAP;
    const uint2* __restrict__ xh4 = (const uint2*)g_ah;   // row = 48 uint2

    float ax = 0.f, ay = 0.f, az = 0.f, aw = 0.f;
    int s = 0;
    for (; s + 4 <= n; s += 4) {
        int4 b4 = __ldg((const int4*)(b + s));
        uint2 v0 = __ldg(&xh4[b4.x * 48 + j4]);
        uint2 v1 = __ldg(&xh4[b4.y * 48 + j4]);
        uint2 v2 = __ldg(&xh4[b4.z * 48 + j4]);
        uint2 v3 = __ldg(&xh4[b4.w * 48 + j4]);
        float2 p0 = __half22float2(*(__half2*)&v0.x);
        float2 q0 = __half22float2(*(__half2*)&v0.y);
        float2 p1 = __half22float2(*(__half2*)&v1.x);
        float2 q1 = __half22float2(*(__half2*)&v1.y);
        float2 p2 = __half22float2(*(__half2*)&v2.x);
        float2 q2 = __half22float2(*(__half2*)&v2.y);
        float2 p3 = __half22float2(*(__half2*)&v3.x);
        float2 q3 = __half22float2(*(__half2*)&v3.y);
        ax += (p0.x + p1.x) + (p2.x + p3.x);
        ay += (p0.y + p1.y) + (p2.y + p3.y);
        az += (q0.x + q1.x) + (q2.x + q3.x);
        aw += (q0.y + q1.y) + (q2.y + q3.y);
    }
    for (; s < n; s++) {
        int sn = __ldg(&b[s]);
        uint2 v = __ldg(&xh4[sn * 48 + j4]);
        float2 p = __half22float2(*(__half2*)&v.x);
        float2 q = __half22float2(*(__half2*)&v.y);
        ax += p.x; ay += p.y; az += q.x; aw += q.y;
    }

    if (deg <= CAP) {
        // fast path: normalize + fp16 store into g_ah cols 96..191
        float inv = 1.0f / (float)((deg > 1) ? deg : 1);
        __half2 h0 = __floats2half2_rn(ax * inv, ay * inv);
        __half2 h1 = __floats2half2_rn(az * inv, aw * inv);
        uint2 o;
        o.x = *(uint32_t*)&h0;
        o.y = *(uint32_t*)&h1;
        ((uint2*)g_ah)[node * 48 + 24 + j4] = o;
    } else {
        // overflow row: raw fp32 partial sums; ovf_fix completes it
        float4 o = make_float4(ax, ay, az, aw);
        ((float4*)g_agg)[node * 24 + j4] = o;
    }
}

// ---------------------------------------------------------------------------
// Overflow fix: ONE block. Phase 1: red-add remaining x[src] into g_agg.
// Phase 2: normalize + fp16-convert affected rows (idempotent per row).
// novf == 0 (typical) -> immediate exit.
// ---------------------------------------------------------------------------
__global__ void ovf_fix_kernel(const float* __restrict__ x) {
    int n = g_novf;
    if (n == 0) return;
    int total = n * 24;
    for (int t = threadIdx.x; t < total; t += blockDim.x) {
        int e = t / 24, c = t % 24;
        int src = g_ovf[2 * e + 0];
        int dst = g_ovf[2 * e + 1];
        float4 v = ((const float4*)(x + (size_t)src * DIM))[c];
        float* p = g_agg + (size_t)dst * DIM + c * 4;
        asm volatile("red.global.add.v4.f32 [%0], {%1,%2,%3,%4};"
                     :: "l"(p), "f"(v.x), "f"(v.y), "f"(v.z), "f"(v.w)
                     : "memory");
    }
    __threadfence();
    __syncthreads();
    for (int t = threadIdx.x; t < total; t += blockDim.x) {
        int e = t / 24, c = t % 24;
        int dst = g_ovf[2 * e + 1];
        float inv = 1.0f / (float)g_cnt[dst];
        float4 v = ((const float4*)g_agg)[dst * 24 + c];
        __half2 h0 = __floats2half2_rn(v.x * inv, v.y * inv);
        __half2 h1 = __floats2half2_rn(v.z * inv, v.w * inv);
        uint2 o;
        o.x = *(uint32_t*)&h0;
        o.y = *(uint32_t*)&h1;
        ((uint2*)g_ah)[dst * 48 + 24 + c] = o;
    }
}

// ---------------------------------------------------------------------------
// HMMA GEMM: out[50000,96] = g_ah[50000,192] @ g_wh[96,192]^T + (bs+bn)
// BM=128 rows/block, 4 warps; warp = 32 rows x 96 cols = 2x12 m16n8k16 tiles.
// ---------------------------------------------------------------------------
#define HBM 128
#define HPITCH 200
#define HMMA_THREADS 128
#define HMMA_BLOCKS ((N_NODES + HBM - 1) / HBM)   // 391
#define HMMA_SMEM ((HBM + DIM) * HPITCH * 2)      // 89600 bytes

__device__ __forceinline__ uint32_t smem_u32(const void* p) {
    return (uint32_t)__cvta_generic_to_shared(p);
}
__device__ __forceinline__ void ldsm_x4(uint32_t& r0, uint32_t& r1,
                                        uint32_t& r2, uint32_t& r3,
                                        uint32_t addr) {
    asm volatile("ldmatrix.sync.aligned.m8n8.x4.shared.b16 {%0,%1,%2,%3}, [%4];"
                 : "=r"(r0), "=r"(r1), "=r"(r2), "=r"(r3) : "r"(addr));
}
__device__ __forceinline__ void mma16816(float* d, const uint32_t* a,
                                         const uint32_t* b) {
    asm volatile(
        "mma.sync.aligned.m16n8k16.row.col.f32.f16.f16.f32 "
        "{%0,%1,%2,%3}, {%4,%5,%6,%7}, {%8,%9}, {%0,%1,%2,%3};"
        : "+f"(d[0]), "+f"(d[1]), "+f"(d[2]), "+f"(d[3])
        : "r"(a[0]), "r"(a[1]), "r"(a[2]), "r"(a[3]), "r"(b[0]), "r"(b[1]));
}

__global__ __launch_bounds__(HMMA_THREADS)
void hmma_kernel(const float* __restrict__ bs, const float* __restrict__ bn,
                 float* __restrict__ out) {
    extern __shared__ __half hsm[];
    __half* sA = hsm;                      // [HBM][HPITCH]
    __half* sB = hsm + HBM * HPITCH;       // [DIM][HPITCH]
    __shared__ float sBias[DIM];

    const int tid = threadIdx.x;
    const int warp = tid >> 5;
    const int lane = tid & 31;
    const int rowBase = blockIdx.x * HBM;

    if (tid < DIM) sBias[tid] = bs[tid] + bn[tid];

    #pragma unroll
    for (int it = 0; it < 24; it++) {
        int idx = it * HMMA_THREADS + tid;
        int m = idx / 24, q = idx % 24;
        int row = rowBase + m;
        uint4 v = make_uint4(0u, 0u, 0u, 0u);
        if (row < N_NODES)
            v = ((const uint4*)(g_ah + (size_t)row * KTOT))[q];
        *(uint4*)&sA[m * HPITCH + q * 8] = v;
    }
    #pragma unroll
    for (int it = 0; it < 18; it++) {
        int idx = it * HMMA_THREADS + tid;
        int j = idx / 24, q = idx % 24;
        *(uint4*)&sB[j * HPITCH + q * 8] = ((const uint4*)(g_wh + j * KTOT))[q];
    }
    __syncthreads();

    float acc[2][12][4];
    #pragma unroll
    for (int mt = 0; mt < 2; mt++)
        #pragma unroll
        for (int nt = 0; nt < 12; nt++)
            #pragma unroll
            for (int i = 0; i < 4; i++) acc[mt][nt][i] = 0.0f;

    const int mrow0 = warp * 32;

    #pragma unroll 3
    for (int k16 = 0; k16 < KTOT / 16; k16++) {
        int k0 = k16 * 16;
        uint32_t a[2][4];
        #pragma unroll
        for (int mt = 0; mt < 2; mt++) {
            uint32_t addr = smem_u32(
                &sA[(mrow0 + mt * 16 + (lane & 15)) * HPITCH +
                    k0 + ((lane >> 4) << 3)]);
            ldsm_x4(a[mt][0], a[mt][1], a[mt][2], a[mt][3], addr);
        }
        uint32_t b[12][2];
        #pragma unroll
        for (int np = 0; np < 6; np++) {
            int n0 = np * 16;
            int nrow = n0 + ((lane >> 4) << 3) + (lane & 7);
            int kcol = k0 + (((lane >> 3) & 1) << 3);
            uint32_t addr = smem_u32(&sB[nrow * HPITCH + kcol]);
            uint32_t r0, r1, r2, r3;
            ldsm_x4(r0, r1, r2, r3, addr);
            b[2 * np + 0][0] = r0; b[2 * np + 0][1] = r1;
            b[2 * np + 1][0] = r2; b[2 * np + 1][1] = r3;
        }
        #pragma unroll
        for (int mt = 0; mt < 2; mt++)
            #pragma unroll
            for (int nt = 0; nt < 12; nt++)
                mma16816(acc[mt][nt], a[mt], b[nt]);
    }

    #pragma unroll
    for (int mt = 0; mt < 2; mt++) {
        int r0 = rowBase + mrow0 + mt * 16 + (lane >> 2);
        #pragma unroll
        for (int nt = 0; nt < 12; nt++) {
            int c = nt * 8 + (lane & 3) * 2;
            float bx = sBias[c], by = sBias[c + 1];
            if (r0 < N_NODES) {
                float2 v0 = make_float2(acc[mt][nt][0] + bx,
                                        acc[mt][nt][1] + by);
                *(float2*)(out + (size_t)r0 * DIM + c) = v0;
            }
            int r1 = r0 + 8;
            if (r1 < N_NODES) {
                float2 v1 = make_float2(acc[mt][nt][2] + bx,
                                        acc[mt][nt][3] + by);
                *(float2*)(out + (size_t)r1 * DIM + c) = v1;
            }
        }
    }
}

// ---------------------------------------------------------------------------
extern "C" void kernel_launch(void* const* d_in, const int* in_sizes, int n_in,
                              void* d_out, int out_size) {
    const float* x        = (const float*)d_in[0];
    const int*   ei       = (const int*)d_in[1];
    const float* W_self   = (const float*)d_in[2];
    const float* b_self   = (const float*)d_in[3];
    const float* W_neigh  = (const float*)d_in[4];
    const float* b_neigh  = (const float*)d_in[5];
    float*       out      = (float*)d_out;

    static void* cnt_ptr = nullptr;
    static void* novf_ptr = nullptr;
    if (!cnt_ptr) {
        cudaGetSymbolAddress(&cnt_ptr, g_cnt);
        cudaGetSymbolAddress(&novf_ptr, g_novf);
        cudaFuncSetAttribute(hmma_kernel,
                             cudaFuncAttributeMaxDynamicSharedMemorySize,
                             HMMA_SMEM);
    }

    cudaMemsetAsync(cnt_ptr, 0, (size_t)N_NODES * sizeof(int));
    cudaMemsetAsync(novf_ptr, 0, sizeof(int));

    convert_kernel<<<(NXH2 + NWH2 + 255) / 256, 256>>>(x, W_self, W_neigh);
    fill_kernel<<<(N_EDGES + 255) / 256, 256>>>(ei);
    gather_kernel<<<(N_NODES + 7) / 8, 192>>>();
    ovf_fix_kernel<<<1, 256>>>(x);
    hmma_kernel<<<HMMA_BLOCKS, HMMA_THREADS, HMMA_SMEM>>>(b_self, b_neigh, out);
}